// round 9
// baseline (speedup 1.0000x reference)
#include <cuda_runtime.h>
#include <cuda_bf16.h>
#include <cstdint>

#define NTOK 6272
#define CDIM 1024
#define HEADS 16
#define HD 64
#define SFR 32
#define PTOK 196
#define MKV 1960
#define KT 32
#define NT 62          // 62*32 = 1984 >= 1960
#define MKPAD 1984

#define KDIM 1024
#define NQKV 3072

// Scratch (no allocations anywhere)
__device__ float g_qkv[3u * HEADS * NTOK * HD];
__device__ __nv_bfloat16 g_ahi[(size_t)NTOK * KDIM];
__device__ __nv_bfloat16 g_alo[(size_t)NTOK * KDIM];
__device__ __nv_bfloat16 g_wqhi[(size_t)NQKV * KDIM];
__device__ __nv_bfloat16 g_wqlo[(size_t)NQKV * KDIM];
__device__ __nv_bfloat16 g_wphi[(size_t)1024 * KDIM];
__device__ __nv_bfloat16 g_wplo[(size_t)1024 * KDIM];
__device__ __nv_bfloat16 g_qhi[(size_t)HEADS * NTOK * HD];
__device__ __nv_bfloat16 g_qlo[(size_t)HEADS * NTOK * HD];
__device__ __nv_bfloat16 g_khi[(size_t)HEADS * NTOK * HD];
__device__ __nv_bfloat16 g_klo[(size_t)HEADS * NTOK * HD];
__device__ __nv_bfloat16 g_vhi[(size_t)HEADS * NTOK * HD];
__device__ __nv_bfloat16 g_vlo[(size_t)HEADS * NTOK * HD];
__device__ int   g_gidx2[SFR * MKPAD];
__device__ float g_bias2[SFR * MKPAD];

// ---------------------------------------------------------------------------
// helpers
// ---------------------------------------------------------------------------
__device__ __forceinline__ uint32_t smem_u32(const void* p) {
    uint32_t a;
    asm("{ .reg .u64 t; cvta.to.shared.u64 t, %1; cvt.u32.u64 %0, t; }"
        : "=r"(a) : "l"(p));
    return a;
}
__device__ __forceinline__ void ldsm4(uint32_t addr, uint32_t& r0, uint32_t& r1,
                                      uint32_t& r2, uint32_t& r3) {
    asm volatile("ldmatrix.sync.aligned.m8n8.x4.shared.b16 {%0,%1,%2,%3}, [%4];"
                 : "=r"(r0), "=r"(r1), "=r"(r2), "=r"(r3) : "r"(addr));
}
__device__ __forceinline__ void ldsm4t(uint32_t addr, uint32_t& r0, uint32_t& r1,
                                       uint32_t& r2, uint32_t& r3) {
    asm volatile("ldmatrix.sync.aligned.m8n8.x4.trans.shared.b16 {%0,%1,%2,%3}, [%4];"
                 : "=r"(r0), "=r"(r1), "=r"(r2), "=r"(r3) : "r"(addr));
}
__device__ __forceinline__ void mma_bf16(float& d0, float& d1, float& d2, float& d3,
                                         uint32_t a0, uint32_t a1, uint32_t a2, uint32_t a3,
                                         uint32_t b0, uint32_t b1) {
    asm volatile(
        "mma.sync.aligned.m16n8k16.row.col.f32.bf16.bf16.f32 "
        "{%0,%1,%2,%3}, {%4,%5,%6,%7}, {%8,%9}, {%0,%1,%2,%3};"
        : "+f"(d0), "+f"(d1), "+f"(d2), "+f"(d3)
        : "r"(a0), "r"(a1), "r"(a2), "r"(a3), "r"(b0), "r"(b1));
}
__device__ __forceinline__ uint32_t pack_bf16(float a, float b) {
    __nv_bfloat162 t;
    t.x = __float2bfloat16_rn(a);
    t.y = __float2bfloat16_rn(b);
    return *(uint32_t*)&t;
}
__device__ __forceinline__ void cpa16(uint32_t dst, const void* src) {
    asm volatile("cp.async.cg.shared.global [%0], [%1], 16;"
                 :: "r"(dst), "l"(src) : "memory");
}
__device__ __forceinline__ void cpa_commit() {
    asm volatile("cp.async.commit_group;" ::: "memory");
}
__device__ __forceinline__ void cpa_wait0() {
    asm volatile("cp.async.wait_group 0;" ::: "memory");
}

// ---------------------------------------------------------------------------
// Split fp32 -> bf16 hi/lo planes into g_ahi/g_alo (same layout)
// ---------------------------------------------------------------------------
__global__ void __launch_bounds__(256)
split_kernel(const float* __restrict__ src, int n4)
{
    int i = blockIdx.x * blockDim.x + threadIdx.x;
    if (i >= n4) return;
    float4 a = ((const float4*)src)[i];
    __nv_bfloat16 h0 = __float2bfloat16_rn(a.x);
    __nv_bfloat16 h1 = __float2bfloat16_rn(a.y);
    __nv_bfloat16 h2 = __float2bfloat16_rn(a.z);
    __nv_bfloat16 h3 = __float2bfloat16_rn(a.w);
    __nv_bfloat16 l0 = __float2bfloat16_rn(a.x - __bfloat162float(h0));
    __nv_bfloat16 l1 = __float2bfloat16_rn(a.y - __bfloat162float(h1));
    __nv_bfloat16 l2 = __float2bfloat16_rn(a.z - __bfloat162float(h2));
    __nv_bfloat16 l3 = __float2bfloat16_rn(a.w - __bfloat162float(h3));
    __nv_bfloat162 hh0; hh0.x = h0; hh0.y = h1;
    __nv_bfloat162 hh1; hh1.x = h2; hh1.y = h3;
    __nv_bfloat162 ll0; ll0.x = l0; ll0.y = l1;
    __nv_bfloat162 ll1; ll1.x = l2; ll1.y = l3;
    ((__nv_bfloat162*)g_ahi)[i * 2]     = hh0;
    ((__nv_bfloat162*)g_ahi)[i * 2 + 1] = hh1;
    ((__nv_bfloat162*)g_alo)[i * 2]     = ll0;
    ((__nv_bfloat162*)g_alo)[i * 2 + 1] = ll1;
}

// ---------------------------------------------------------------------------
// Pad/clamp gather indices and fold the static-max shift into the bias.
// ---------------------------------------------------------------------------
__global__ void __launch_bounds__(256)
pad_kernel(const int* __restrict__ gidx, const float* __restrict__ abias)
{
    int i = blockIdx.x * blockDim.x + threadIdx.x;
    if (i >= SFR * MKPAD) return;
    int s = i / MKPAD, j = i - s * MKPAD;
    int jj = (j < MKV) ? j : 0;
    g_gidx2[i] = gidx[s * MKV + jj];
    g_bias2[i] = (j < MKV) ? (abias[s * MKV + j] - 10.f) : -1e9f;
}

// ---------------------------------------------------------------------------
// Transpose + split: W [1024][N] fp32 -> hi/lo [N][1024] bf16
// ---------------------------------------------------------------------------
template <int WHICH>
__global__ void __launch_bounds__(256)
wsplit_kernel(const float* __restrict__ W, int N)
{
    __nv_bfloat16* hi = (WHICH == 0) ? g_wqhi : g_wphi;
    __nv_bfloat16* lo = (WHICH == 0) ? g_wqlo : g_wplo;
    __shared__ float t[32][33];
    int n0 = blockIdx.x * 32, k0 = blockIdx.y * 32;
    int tx = threadIdx.x & 31, ty = threadIdx.x >> 5;
#pragma unroll
    for (int r = 0; r < 4; r++)
        t[ty + r * 8][tx] = W[(size_t)(k0 + ty + r * 8) * N + n0 + tx];
    __syncthreads();
#pragma unroll
    for (int r = 0; r < 4; r++) {
        int n = ty + r * 8;
        float a = t[tx][n];
        __nv_bfloat16 h = __float2bfloat16_rn(a);
        __nv_bfloat16 l = __float2bfloat16_rn(a - __bfloat162float(h));
        size_t o = (size_t)(n0 + n) * KDIM + k0 + tx;
        hi[o] = h;
        lo[o] = l;
    }
}

// ---------------------------------------------------------------------------
// HMMA GEMM v4: k-chunk 32, 2-stage cp.async double buffer, 2 CTAs/SM,
// one barrier per chunk (32 barriers total).
// ---------------------------------------------------------------------------
#define RSTR 40                        // 32 elems + 8 pad -> 80B rows, conflict-free
#define CH_K 32
#define TILE_E (128 * RSTR)            // 5120 elems
#define STAGE_E (4 * TILE_E)           // 20480 elems
#define STAGE_B (STAGE_E * 2)          // 40960 bytes
#define NSTAGE 2
#define GEMM_SMEM (NSTAGE * STAGE_B)   // 81920 bytes
#define OFF_AH 0
#define OFF_AL TILE_E
#define OFF_BH (2 * TILE_E)
#define OFF_BL (3 * TILE_E)

template <int MODE>
__global__ void __launch_bounds__(256, 2)
hmma_gemm_kernel(const float* __restrict__ bias, float* __restrict__ Cout, int Nc)
{
    extern __shared__ __nv_bfloat16 smb[];
    const uint32_t su = smem_u32(smb);

    const __nv_bfloat16* Bhi = (MODE == 0) ? g_wqhi : g_wphi;
    const __nv_bfloat16* Blo = (MODE == 0) ? g_wqlo : g_wplo;

    const int tid = threadIdx.x;
    const int wid = tid >> 5;
    const int lane = tid & 31;
    const int wm = wid & 1;
    const int wn = wid >> 1;
    const int bm = blockIdx.y * 128;
    const int bn = blockIdx.x * 128;

    const int grow = tid >> 1;
    const int ghalf = tid & 1;
    const __nv_bfloat16* pAhi = g_ahi + (size_t)(bm + grow) * KDIM + ghalf * 8;
    const __nv_bfloat16* pAlo = g_alo + (size_t)(bm + grow) * KDIM + ghalf * 8;
    const __nv_bfloat16* pBhi = Bhi + (size_t)(bn + grow) * KDIM + ghalf * 8;
    const __nv_bfloat16* pBlo = Blo + (size_t)(bn + grow) * KDIM + ghalf * 8;
    const uint32_t sstore = (uint32_t)(grow * RSTR + ghalf * 8) * 2;   // bytes

    const uint32_t aAddr = (uint32_t)((wm * 64 + (lane & 15)) * RSTR + (lane >> 4) * 8) * 2;
    const uint32_t bAddr = (uint32_t)((wn * 32 + (lane & 7) + ((lane >> 4) & 1) * 8) * RSTR
                                      + ((lane >> 3) & 1) * 8) * 2;

    float acc[4][4][4];
#pragma unroll
    for (int mf = 0; mf < 4; mf++)
#pragma unroll
        for (int nf = 0; nf < 4; nf++)
#pragma unroll
            for (int e = 0; e < 4; e++) acc[mf][nf][e] = 0.f;

    const int NCHUNK = KDIM / CH_K;    // 32

    // issue chunk c1 into stage slot b (each thread: 2 x 16B per array)
    auto issue_chunk = [&](int c1, int b) {
        uint32_t sb = su + (uint32_t)b * STAGE_B + sstore;
        int ko = c1 * CH_K;
        cpa16(sb + OFF_AH * 2,      pAhi + ko);
        cpa16(sb + OFF_AH * 2 + 32, pAhi + ko + 16);
        cpa16(sb + OFF_AL * 2,      pAlo + ko);
        cpa16(sb + OFF_AL * 2 + 32, pAlo + ko + 16);
        cpa16(sb + OFF_BH * 2,      pBhi + ko);
        cpa16(sb + OFF_BH * 2 + 32, pBhi + ko + 16);
        cpa16(sb + OFF_BL * 2,      pBlo + ko);
        cpa16(sb + OFF_BL * 2 + 32, pBlo + ko + 16);
    };

    issue_chunk(0, 0);
    cpa_commit();

    for (int c = 0; c < NCHUNK; c++) {
        cpa_wait0();                   // chunk c's copy complete
        __syncthreads();               // all warps done computing chunk c-1

        if (c + 1 < NCHUNK) issue_chunk(c + 1, (c + 1) & 1);
        cpa_commit();

        const uint32_t sb = su + (uint32_t)(c & 1) * STAGE_B;
#pragma unroll
        for (int kf = 0; kf < 2; kf++) {
            const uint32_t kfo = kf * 32;   // 16 elems
            uint32_t bh[8], bl[8];
            ldsm4(sb + OFF_BH * 2 + bAddr + kfo, bh[0], bh[1], bh[2], bh[3]);
            ldsm4(sb + OFF_BH * 2 + bAddr + kfo + 16 * RSTR * 2, bh[4], bh[5], bh[6], bh[7]);
            ldsm4(sb + OFF_BL * 2 + bAddr + kfo, bl[0], bl[1], bl[2], bl[3]);
            ldsm4(sb + OFF_BL * 2 + bAddr + kfo + 16 * RSTR * 2, bl[4], bl[5], bl[6], bl[7]);

#pragma unroll
            for (int mf = 0; mf < 4; mf++) {
                uint32_t a0, a1, a2, a3;
                ldsm4(sb + OFF_AH * 2 + aAddr + kfo + mf * 16 * RSTR * 2, a0, a1, a2, a3);
#pragma unroll
                for (int nf = 0; nf < 4; nf++)
                    mma_bf16(acc[mf][nf][0], acc[mf][nf][1], acc[mf][nf][2], acc[mf][nf][3],
                             a0, a1, a2, a3, bh[nf * 2], bh[nf * 2 + 1]);
#pragma unroll
                for (int nf = 0; nf < 4; nf++)
                    mma_bf16(acc[mf][nf][0], acc[mf][nf][1], acc[mf][nf][2], acc[mf][nf][3],
                             a0, a1, a2, a3, bl[nf * 2], bl[nf * 2 + 1]);
                ldsm4(sb + OFF_AL * 2 + aAddr + kfo + mf * 16 * RSTR * 2, a0, a1, a2, a3);
#pragma unroll
                for (int nf = 0; nf < 4; nf++)
                    mma_bf16(acc[mf][nf][0], acc[mf][nf][1], acc[mf][nf][2], acc[mf][nf][3],
                             a0, a1, a2, a3, bh[nf * 2], bh[nf * 2 + 1]);
            }
        }
    }

#pragma unroll
    for (int mf = 0; mf < 4; mf++) {
#pragma unroll
        for (int nf = 0; nf < 4; nf++) {
            int m0 = bm + wm * 64 + mf * 16 + (lane >> 2);
            int col = bn + wn * 32 + nf * 8 + (lane & 3) * 2;
            float2 bb = *(const float2*)&bias[col];
            float2 v0, v1;
            v0.x = acc[mf][nf][0] + bb.x;
            v0.y = acc[mf][nf][1] + bb.y;
            v1.x = acc[mf][nf][2] + bb.x;
            v1.y = acc[mf][nf][3] + bb.y;
            if (MODE == 0) {
                int part = col >> 10;
                int h = (col >> 6) & (HEADS - 1);
                int d = col & 63;
                float* base = &g_qkv[(((size_t)part * HEADS + h) * NTOK) * HD + d];
                *(float2*)(base + (size_t)m0 * HD) = v0;
                *(float2*)(base + (size_t)(m0 + 8) * HD) = v1;
            } else {
                *(float2*)&Cout[(size_t)m0 * Nc + col] = v0;
                *(float2*)&Cout[(size_t)(m0 + 8) * Nc + col] = v1;
            }
        }
    }
}

// ---------------------------------------------------------------------------
// LayerNorm + bf16 hi/lo split of q, k, and passthrough split of v.
// ---------------------------------------------------------------------------
__global__ void __launch_bounds__(256)
ln2_kernel(const float* __restrict__ qg, const float* __restrict__ qb,
           const float* __restrict__ kg, const float* __restrict__ kb)
{
    const int HN = HEADS * NTOK;
    int warp = (blockIdx.x * blockDim.x + threadIdx.x) >> 5;
    int lane = threadIdx.x & 31;
    if (warp >= 3 * HN) return;

    const float* v = g_qkv + (size_t)warp * HD;
    float2 x = *(const float2*)&v[lane * 2];
    int part = warp / HN;
    int local = warp - part * HN;

    if (part < 2) {
        float s = x.x + x.y;
#pragma unroll
        for (int o = 16; o; o >>= 1) s += __shfl_xor_sync(0xffffffffu, s, o);
        float mu = s * (1.f / 64.f);
        float dx = x.x - mu, dy = x.y - mu;
        float ss = dx * dx + dy * dy;
#pragma unroll
        for (int o = 16; o; o >>= 1) ss += __shfl_xor_sync(0xffffffffu, ss, o);
        float rstd = rsqrtf(ss * (1.f / 64.f) + 1e-6f);
        const float* g = (part == 0) ? qg : kg;
        const float* b = (part == 0) ? qb : kb;
        x.x = dx * rstd * g[lane * 2] + b[lane * 2];
        x.y = dy * rstd * g[lane * 2 + 1] + b[lane * 2 + 1];
    }

    __nv_bfloat16* hi = (part == 0) ? g_qhi : (part == 1) ? g_khi : g_vhi;
    __nv_bfloat16* lo = (part == 0) ? g_qlo : (part == 1) ? g_klo : g_vlo;
    __nv_bfloat16 h0 = __float2bfloat16_rn(x.x);
    __nv_bfloat16 h1 = __float2bfloat16_rn(x.y);
    __nv_bfloat16 l0 = __float2bfloat16_rn(x.x - __bfloat162float(h0));
    __nv_bfloat16 l1 = __float2bfloat16_rn(x.y - __bfloat162float(h1));
    __nv_bfloat162 ph; ph.x = h0; ph.y = h1;
    __nv_bfloat162 pl; pl.x = l0; pl.y = l1;
    *(__nv_bfloat162*)&hi[(size_t)local * HD + lane * 2] = ph;
    *(__nv_bfloat162*)&lo[(size_t)local * HD + lane * 2] = pl;
}

// ---------------------------------------------------------------------------
// HMMA flash attention v3: Q hi AND lo in smem (low registers), cp.async
// double-buffered K/V tiles, 2 CTAs per SM.
// ---------------------------------------------------------------------------
#define AST 72
#define QLO_OFF 0
#define QHI_OFF (224 * AST)                       // 16128
#define KARR (KT * AST)                           // 2304
#define TILE_ELEMS (4 * KARR)                     // 9216
#define TILE_OFF (2 * 224 * AST)                  // 32256
#define BIAS_OFF (TILE_OFF + 2 * TILE_ELEMS)      // 50688 elems
#define AT_SMEM_BYTES (BIAS_OFF * 2 + 2 * KT * 4)   // 101632

__global__ void __launch_bounds__(224, 2)
attn6_kernel()
{
    extern __shared__ __nv_bfloat16 smb2[];
    const uint32_t su = smem_u32(smb2);

    const int s = blockIdx.x, h = blockIdx.y;
    const int tid = threadIdx.x, wid = tid >> 5, lane = tid & 31;
    const int m0 = wid * 32;

    const __nv_bfloat16* qh  = g_qhi + ((size_t)h * NTOK + (size_t)s * PTOK) * HD;
    const __nv_bfloat16* qlg = g_qlo + ((size_t)h * NTOK + (size_t)s * PTOK) * HD;
    const __nv_bfloat16* kh = g_khi + (size_t)h * NTOK * HD;
    const __nv_bfloat16* kl = g_klo + (size_t)h * NTOK * HD;
    const __nv_bfloat16* vh = g_vhi + (size_t)h * NTOK * HD;
    const __nv_bfloat16* vl = g_vlo + (size_t)h * NTOK * HD;

    // Q hi + lo -> smem (row per thread, clamp rows >= 196)
    {
        int row = tid;
        int srcr = row < PTOK ? row : PTOK - 1;
        const uint4* pl = (const uint4*)(qlg + (size_t)srcr * HD);
        const uint4* ph = (const uint4*)(qh + (size_t)srcr * HD);
#pragma unroll
        for (int j = 0; j < 8; j++) {
            *(uint4*)&smb2[QLO_OFF + row * AST + j * 8] = pl[j];
            *(uint4*)&smb2[QHI_OFF + row * AST + j * 8] = ph[j];
        }
    }

    float o[2][8][4];
    float lsum[2][2];
#pragma unroll
    for (int mf = 0; mf < 2; mf++) {
        lsum[mf][0] = 0.f; lsum[mf][1] = 0.f;
#pragma unroll
        for (int nf = 0; nf < 8; nf++)
#pragma unroll
            for (int e = 0; e < 4; e++) o[mf][nf][e] = 0.f;
    }

    const int pbase = s * MKPAD;

    // per-lane ldsm fragment addresses (bytes; tile buffer offset added later)
    const uint32_t kaddr = su + 2 * (TILE_OFF
        + ((lane & 7) + ((lane >> 4) & 1) * 8) * AST + ((lane >> 3) & 1) * 8);
    const uint32_t vaddr = su + 2 * (TILE_OFF + 2 * KARR
        + ((lane & 7) + ((lane >> 3) & 1) * 8) * AST + ((lane >> 4) & 1) * 8);
    const uint32_t qladdr = su + 2 * (QLO_OFF + (m0 + (lane & 15)) * AST + (lane >> 4) * 8);
    const uint32_t qhaddr = su + 2 * (QHI_OFF + (m0 + (lane & 15)) * AST + (lane >> 4) * 8);

    // issue gathered tile t1 into buffer b via cp.async
    auto issue_tile = [&](int t1, int b) {
        const int ibase = pbase + t1 * KT;
#pragma unroll
        for (int it = 0; it < 5; it++) {
            int slot = tid + it * 224;
            if (slot < 1024) {
                int a = slot >> 8, r = (slot >> 3) & 31, seg = slot & 7;
                int tok = g_gidx2[ibase + r];
                const __nv_bfloat16* bp = (a == 0) ? kh : (a == 1) ? kl
                                         : (a == 2) ? vh : vl;
                cpa16(su + 2 * (TILE_OFF + b * TILE_ELEMS + a * KARR + r * AST + seg * 8),
                      bp + (size_t)tok * HD + seg * 8);
            }
        }
        if (tid < 8)
            cpa16(su + 2 * BIAS_OFF + b * 128 + tid * 16, &g_bias2[ibase + tid * 4]);
    };

    issue_tile(0, 0);
    cpa_commit();

    for (int t = 0; t < NT; t++) {
        cpa_wait0();                    // tile t's copies complete
        __syncthreads();                // all warps done computing tile t-1

        if (t + 1 < NT) issue_tile(t + 1, (t + 1) & 1);
        cpa_commit();

        const uint32_t boff = (uint32_t)(t & 1) * TILE_ELEMS * 2;
        const float* Bs = (const float*)(smb2 + BIAS_OFF) + (t & 1) * 32;

        // ---- QK: 3-product bf16 split (Q hi/lo from smem via ldsm) ----
        float sc[2][4][4];
#pragma unroll
        for (int mf = 0; mf < 2; mf++)
#pragma unroll
            for (int nf = 0; nf < 4; nf++)
#pragma unroll
                for (int e = 0; e < 4; e++) sc[mf][nf][e] = 0.f;

#pragma unroll
        for (int kf = 0; kf < 4; kf++) {
            uint32_t bh0[4], bh1[4], bl0[4], bl1[4];
            ldsm4(kaddr + boff + kf * 32, bh0[0], bh0[1], bh0[2], bh0[3]);
            ldsm4(kaddr + boff + kf * 32 + 16 * AST * 2, bh1[0], bh1[1], bh1[2], bh1[3]);
            ldsm4(kaddr + boff + KARR * 2 + kf * 32, bl0[0], bl0[1], bl0[2], bl0[3]);
            ldsm4(kaddr + boff + KARR * 2 + kf * 32 + 16 * AST * 2,
                  bl1[0], bl1[1], bl1[2], bl1[3]);
#pragma unroll
            for (int mf = 0; mf < 2; mf++) {
                uint32_t q0, q1, q2, q3;
                ldsm4(qhaddr + mf * 16 * AST * 2 + kf * 32, q0, q1, q2, q3);
                mma_bf16(sc[mf][0][0], sc[mf][0][1], sc[mf][0][2], sc[mf][0][3],
                         q0, q1, q2, q3, bh0[0], bh0[1]);
                mma_bf16(sc[mf][1][0], sc[mf][1][1], sc[mf][1][2], sc[mf][1][3],
                         q0, q1, q2, q3, bh0[2], bh0[3]);
                mma_bf16(sc[mf][2][0], sc[mf][2][1], sc[mf][2][2], sc[mf][2][3],
                         q0, q1, q2, q3, bh1[0], bh1[1]);
                mma_bf16(sc[mf][3][0], sc[mf][3][1], sc[mf][3][2], sc[mf][3][3],
                         q0, q1, q2, q3, bh1[2], bh1[3]);
                mma_bf16(sc[mf][0][0], sc[mf][0][1], sc[mf][0][2], sc[mf][0][3],
                         q0, q1, q2, q3, bl0[0], bl0[1]);
                mma_bf16(sc[mf][1][0], sc[mf][1][1], sc[mf][1][2], sc[mf][1][3],
                         q0, q1, q2, q3, bl0[2], bl0[3]);
                mma_bf16(sc[mf][2][0], sc[mf][2][1], sc[mf][2][2], sc[mf][2][3],
                         q0, q1, q2, q3, bl1[0], bl1[1]);
                mma_bf16(sc[mf][3][0], sc[mf][3][1], sc[mf][3][2], sc[mf][3][3],
                         q0, q1, q2, q3, bl1[2], bl1[3]);
                ldsm4(qladdr + mf * 16 * AST * 2 + kf * 32, q0, q1, q2, q3);
                mma_bf16(sc[mf][0][0], sc[mf][0][1], sc[mf][0][2], sc[mf][0][3],
                         q0, q1, q2, q3, bh0[0], bh0[1]);
                mma_bf16(sc[mf][1][0], sc[mf][1][1], sc[mf][1][2], sc[mf][1][3],
                         q0, q1, q2, q3, bh0[2], bh0[3]);
                mma_bf16(sc[mf][2][0], sc[mf][2][1], sc[mf][2][2], sc[mf][2][3],
                         q0, q1, q2, q3, bh1[0], bh1[1]);
                mma_bf16(sc[mf][3][0], sc[mf][3][1], sc[mf][3][2], sc[mf][3][3],
                         q0, q1, q2, q3, bh1[2], bh1[3]);
            }
        }

        // ---- softmax weights + P split ----
        uint32_t phi[2][2][4], plo[2][2][4];
#pragma unroll
        for (int mf = 0; mf < 2; mf++) {
#pragma unroll
            for (int nf = 0; nf < 4; nf++) {
                float2 bb = *(const float2*)&Bs[nf * 8 + (lane & 3) * 2];
                float p0 = __expf(fmaf(sc[mf][nf][0], 0.125f, bb.x));
                float p1 = __expf(fmaf(sc[mf][nf][1], 0.125f, bb.y));
                float p2 = __expf(fmaf(sc[mf][nf][2], 0.125f, bb.x));
                float p3 = __expf(fmaf(sc[mf][nf][3], 0.125f, bb.y));
                lsum[mf][0] += p0 + p1;
                lsum[mf][1] += p2 + p3;
                uint32_t h01 = pack_bf16(p0, p1);
                uint32_t h23 = pack_bf16(p2, p3);
                __nv_bfloat162 hv01 = *(__nv_bfloat162*)&h01;
                __nv_bfloat162 hv23 = *(__nv_bfloat162*)&h23;
                uint32_t l01 = pack_bf16(p0 - __bfloat162float(hv01.x),
                                         p1 - __bfloat162float(hv01.y));
                uint32_t l23 = pack_bf16(p2 - __bfloat162float(hv23.x),
                                         p3 - __bfloat162float(hv23.y));
                int kf2 = nf >> 1, hf = (nf & 1) * 2;
                phi[mf][kf2][hf] = h01; phi[mf][kf2][hf + 1] = h23;
                plo[mf][kf2][hf] = l01; plo[mf][kf2][hf + 1] = l23;
            }
        }

        // ---- PV: 3-product split, V via ldsm.trans ----
#pragma unroll
        for (int kf = 0; kf < 2; kf++) {
            uint32_t vhf[16], vlf[16];
#pragma unroll
            for (int db = 0; db < 4; db++) {
                ldsm4t(vaddr + boff + kf * (16 * AST * 2) + db * 32,
                       vhf[db * 4], vhf[db * 4 + 1], vhf[db * 4 + 2], vhf[db * 4 + 3]);
                ldsm4t(vaddr + boff + KARR * 2 + kf * (16 * AST * 2) + db * 32,
                       vlf[db * 4], vlf[db * 4 + 1], vlf[db * 4 + 2], vlf[db * 4 + 3]);
            }
#pragma unroll
            for (int mf = 0; mf < 2; mf++) {
#pragma unroll
                for (int nfd = 0; nfd < 8; nfd++) {
                    int vi = (nfd >> 1) * 4 + (nfd & 1) * 2;
                    mma_bf16(o[mf][nfd][0], o[mf][nfd][1], o[mf][nfd][2], o[mf][nfd][3],
                             phi[mf][kf][0], phi[mf][kf][1], phi[mf][kf][2], phi[mf][kf][3],
                             vhf[vi], vhf[vi + 1]);
                    mma_bf16(o[mf][nfd][0], o[mf][nfd][1], o[mf][nfd][2], o[mf][nfd][3],
                             phi[mf][kf][0], phi[mf][kf][1], phi[mf][kf][2], phi[mf][kf][3],
                             vlf[vi], vlf[vi + 1]);
                    mma_bf16(o[mf][nfd][0], o[mf][nfd][1], o[mf][nfd][2], o[mf][nfd][3],
                             plo[mf][kf][0], plo[mf][kf][1], plo[mf][kf][2], plo[mf][kf][3],
                             vhf[vi], vhf[vi + 1]);
                }
            }
        }
    }

#pragma unroll
    for (int mf = 0; mf < 2; mf++) {
#pragma unroll
        for (int j = 0; j < 2; j++) {
            float v = lsum[mf][j];
            v += __shfl_xor_sync(0xffffffffu, v, 1);
            v += __shfl_xor_sync(0xffffffffu, v, 2);
            lsum[mf][j] = v;
        }
    }

    {
        int r = lane >> 2, c2 = (lane & 3) * 2;
#pragma unroll
        for (int mf = 0; mf < 2; mf++) {
            int rowq0 = m0 + mf * 16 + r;
            int rowq1 = rowq0 + 8;
            float i0 = 1.f / lsum[mf][0];
            float i1 = 1.f / lsum[mf][1];
            if (rowq0 < PTOK) {
                size_t base = (size_t)(s * PTOK + rowq0) * CDIM + h * HD + c2;
#pragma unroll
                for (int nfd = 0; nfd < 8; nfd++) {
                    float f0 = o[mf][nfd][0] * i0;
                    float f1 = o[mf][nfd][1] * i0;
                    uint32_t hp = pack_bf16(f0, f1);
                    __nv_bfloat162 hv = *(__nv_bfloat162*)&hp;
                    uint32_t lp = pack_bf16(f0 - __bfloat162float(hv.x),
                                            f1 - __bfloat162float(hv.y));
                    *(uint32_t*)&g_ahi[base + nfd * 8] = hp;
                    *(uint32_t*)&g_alo[base + nfd * 8] = lp;
                }
            }
            if (rowq1 < PTOK) {
                size_t base = (size_t)(s * PTOK + rowq1) * CDIM + h * HD + c2;
#pragma unroll
                for (int nfd = 0; nfd < 8; nfd++) {
                    float f0 = o[mf][nfd][2] * i1;
                    float f1 = o[mf][nfd][3] * i1;
                    uint32_t hp = pack_bf16(f0, f1);
                    __nv_bfloat162 hv = *(__nv_bfloat162*)&hp;
                    uint32_t lp = pack_bf16(f0 - __bfloat162float(hv.x),
                                            f1 - __bfloat162float(hv.y));
                    *(uint32_t*)&g_ahi[base + nfd * 8] = hp;
                    *(uint32_t*)&g_alo[base + nfd * 8] = lp;
                }
            }
        }
    }
}

// ---------------------------------------------------------------------------
extern "C" void kernel_launch(void* const* d_in, const int* in_sizes, int n_in,
                              void* d_out, int out_size)
{
    const float* x     = (const float*)d_in[0];
    const float* Wqkv  = (const float*)d_in[1];
    const float* bqkv  = (const float*)d_in[2];
    const float* qg    = (const float*)d_in[3];
    const float* qb    = (const float*)d_in[4];
    const float* kg    = (const float*)d_in[5];
    const float* kb    = (const float*)d_in[6];
    const float* Wproj = (const float*)d_in[7];
    const float* bproj = (const float*)d_in[8];
    const int*   gidx  = (const int*)d_in[9];
    const float* abias = (const float*)d_in[10];
    float* out = (float*)d_out;

    static int attr_set = 0;
    if (!attr_set) {
        cudaFuncSetAttribute(hmma_gemm_kernel<0>,
                             cudaFuncAttributeMaxDynamicSharedMemorySize, GEMM_SMEM);
        cudaFuncSetAttribute(hmma_gemm_kernel<1>,
                             cudaFuncAttributeMaxDynamicSharedMemorySize, GEMM_SMEM);
        cudaFuncSetAttribute(attn6_kernel,
                             cudaFuncAttributeMaxDynamicSharedMemorySize, AT_SMEM_BYTES);
        attr_set = 1;
    }

    const int n4 = NTOK * KDIM / 4;

    // 0) prep: split x, pad gather/bias, transpose+split weights
    split_kernel<<<n4 / 256, 256>>>(x, n4);
    pad_kernel<<<(SFR * MKPAD + 255) / 256, 256>>>(gidx, abias);
    wsplit_kernel<0><<<dim3(NQKV / 32, KDIM / 32), 256>>>(Wqkv, NQKV);
    wsplit_kernel<1><<<dim3(1024 / 32, KDIM / 32), 256>>>(Wproj, 1024);

    // 1) QKV GEMM -> g_qkv fp32
    hmma_gemm_kernel<0><<<dim3(NQKV / 128, NTOK / 128), 256, GEMM_SMEM>>>(
        bqkv, nullptr, NQKV);

    // 2) LayerNorm + bf16 hi/lo split of q/k/v
    {
        int nvec = 3 * HEADS * NTOK;
        ln2_kernel<<<(nvec * 32 + 255) / 256, 256>>>(qg, qb, kg, kb);
    }

    // 3) HMMA flash attention (2 CTAs/SM) -> writes g_ahi/g_alo directly
    attn6_kernel<<<dim3(SFR, HEADS), 224, AT_SMEM_BYTES>>>();

    // 4) proj GEMM -> d_out
    hmma_gemm_kernel<1><<<dim3(1024 / 128, NTOK / 128), 256, GEMM_SMEM>>>(
        bproj, out, 1024);
}

// round 10
// speedup vs baseline: 1.1080x; 1.1080x over previous
#include <cuda_runtime.h>
#include <cuda_bf16.h>
#include <cstdint>

#define NTOK 6272
#define CDIM 1024
#define HEADS 16
#define HD 64
#define SFR 32
#define PTOK 196
#define MKV 1960
#define KT 32
#define MKPAD 1984
#define NSPL 2
#define NT_S 31        // tiles per split
#define KVSPL (NT_S * KT)   // 992

#define KDIM 1024
#define NQKV 3072

// Scratch (no allocations anywhere)
__device__ float g_qkv[3u * HEADS * NTOK * HD];
__device__ __nv_bfloat16 g_ahi[(size_t)NTOK * KDIM];
__device__ __nv_bfloat16 g_alo[(size_t)NTOK * KDIM];
__device__ __nv_bfloat16 g_wqhi[(size_t)NQKV * KDIM];
__device__ __nv_bfloat16 g_wqlo[(size_t)NQKV * KDIM];
__device__ __nv_bfloat16 g_wphi[(size_t)1024 * KDIM];
__device__ __nv_bfloat16 g_wplo[(size_t)1024 * KDIM];
__device__ __nv_bfloat16 g_qhi[(size_t)HEADS * NTOK * HD];
__device__ __nv_bfloat16 g_qlo[(size_t)HEADS * NTOK * HD];
__device__ __nv_bfloat16 g_khi[(size_t)HEADS * NTOK * HD];
__device__ __nv_bfloat16 g_klo[(size_t)HEADS * NTOK * HD];
__device__ __nv_bfloat16 g_vhi[(size_t)HEADS * NTOK * HD];
__device__ __nv_bfloat16 g_vlo[(size_t)HEADS * NTOK * HD];
__device__ int   g_gidx2[SFR * MKPAD];
__device__ float g_bias2[SFR * MKPAD];
__device__ float g_pacc[(size_t)NSPL * SFR * HEADS * PTOK * HD];
__device__ float g_pl[NSPL * SFR * HEADS * PTOK];

// ---------------------------------------------------------------------------
// helpers
// ---------------------------------------------------------------------------
__device__ __forceinline__ uint32_t smem_u32(const void* p) {
    uint32_t a;
    asm("{ .reg .u64 t; cvta.to.shared.u64 t, %1; cvt.u32.u64 %0, t; }"
        : "=r"(a) : "l"(p));
    return a;
}
__device__ __forceinline__ void ldsm4(uint32_t addr, uint32_t& r0, uint32_t& r1,
                                      uint32_t& r2, uint32_t& r3) {
    asm volatile("ldmatrix.sync.aligned.m8n8.x4.shared.b16 {%0,%1,%2,%3}, [%4];"
                 : "=r"(r0), "=r"(r1), "=r"(r2), "=r"(r3) : "r"(addr));
}
__device__ __forceinline__ void ldsm4t(uint32_t addr, uint32_t& r0, uint32_t& r1,
                                       uint32_t& r2, uint32_t& r3) {
    asm volatile("ldmatrix.sync.aligned.m8n8.x4.trans.shared.b16 {%0,%1,%2,%3}, [%4];"
                 : "=r"(r0), "=r"(r1), "=r"(r2), "=r"(r3) : "r"(addr));
}
__device__ __forceinline__ void mma_bf16(float& d0, float& d1, float& d2, float& d3,
                                         uint32_t a0, uint32_t a1, uint32_t a2, uint32_t a3,
                                         uint32_t b0, uint32_t b1) {
    asm volatile(
        "mma.sync.aligned.m16n8k16.row.col.f32.bf16.bf16.f32 "
        "{%0,%1,%2,%3}, {%4,%5,%6,%7}, {%8,%9}, {%0,%1,%2,%3};"
        : "+f"(d0), "+f"(d1), "+f"(d2), "+f"(d3)
        : "r"(a0), "r"(a1), "r"(a2), "r"(a3), "r"(b0), "r"(b1));
}
__device__ __forceinline__ uint32_t pack_bf16(float a, float b) {
    __nv_bfloat162 t;
    t.x = __float2bfloat16_rn(a);
    t.y = __float2bfloat16_rn(b);
    return *(uint32_t*)&t;
}
__device__ __forceinline__ void cpa16(uint32_t dst, const void* src) {
    asm volatile("cp.async.cg.shared.global [%0], [%1], 16;"
                 :: "r"(dst), "l"(src) : "memory");
}
__device__ __forceinline__ void cpa_commit() {
    asm volatile("cp.async.commit_group;" ::: "memory");
}
__device__ __forceinline__ void cpa_wait1() {
    asm volatile("cp.async.wait_group 1;" ::: "memory");
}

// ---------------------------------------------------------------------------
// Split fp32 -> bf16 hi/lo planes into g_ahi/g_alo (same layout)
// ---------------------------------------------------------------------------
__global__ void __launch_bounds__(256)
split_kernel(const float* __restrict__ src, int n4)
{
    int i = blockIdx.x * blockDim.x + threadIdx.x;
    if (i >= n4) return;
    float4 a = ((const float4*)src)[i];
    __nv_bfloat16 h0 = __float2bfloat16_rn(a.x);
    __nv_bfloat16 h1 = __float2bfloat16_rn(a.y);
    __nv_bfloat16 h2 = __float2bfloat16_rn(a.z);
    __nv_bfloat16 h3 = __float2bfloat16_rn(a.w);
    __nv_bfloat16 l0 = __float2bfloat16_rn(a.x - __bfloat162float(h0));
    __nv_bfloat16 l1 = __float2bfloat16_rn(a.y - __bfloat162float(h1));
    __nv_bfloat16 l2 = __float2bfloat16_rn(a.z - __bfloat162float(h2));
    __nv_bfloat16 l3 = __float2bfloat16_rn(a.w - __bfloat162float(h3));
    __nv_bfloat162 hh0; hh0.x = h0; hh0.y = h1;
    __nv_bfloat162 hh1; hh1.x = h2; hh1.y = h3;
    __nv_bfloat162 ll0; ll0.x = l0; ll0.y = l1;
    __nv_bfloat162 ll1; ll1.x = l2; ll1.y = l3;
    ((__nv_bfloat162*)g_ahi)[i * 2]     = hh0;
    ((__nv_bfloat162*)g_ahi)[i * 2 + 1] = hh1;
    ((__nv_bfloat162*)g_alo)[i * 2]     = ll0;
    ((__nv_bfloat162*)g_alo)[i * 2 + 1] = ll1;
}

// ---------------------------------------------------------------------------
// Pad/clamp gather indices and fold the static-max shift into the bias.
// ---------------------------------------------------------------------------
__global__ void __launch_bounds__(256)
pad_kernel(const int* __restrict__ gidx, const float* __restrict__ abias)
{
    int i = blockIdx.x * blockDim.x + threadIdx.x;
    if (i >= SFR * MKPAD) return;
    int s = i / MKPAD, j = i - s * MKPAD;
    int jj = (j < MKV) ? j : 0;
    g_gidx2[i] = gidx[s * MKV + jj];
    g_bias2[i] = (j < MKV) ? (abias[s * MKV + j] - 10.f) : -1e9f;
}

// ---------------------------------------------------------------------------
// Transpose + split: W [1024][N] fp32 -> hi/lo [N][1024] bf16
// ---------------------------------------------------------------------------
template <int WHICH>
__global__ void __launch_bounds__(256)
wsplit_kernel(const float* __restrict__ W, int N)
{
    __nv_bfloat16* hi = (WHICH == 0) ? g_wqhi : g_wphi;
    __nv_bfloat16* lo = (WHICH == 0) ? g_wqlo : g_wplo;
    __shared__ float t[32][33];
    int n0 = blockIdx.x * 32, k0 = blockIdx.y * 32;
    int tx = threadIdx.x & 31, ty = threadIdx.x >> 5;
#pragma unroll
    for (int r = 0; r < 4; r++)
        t[ty + r * 8][tx] = W[(size_t)(k0 + ty + r * 8) * N + n0 + tx];
    __syncthreads();
#pragma unroll
    for (int r = 0; r < 4; r++) {
        int n = ty + r * 8;
        float a = t[tx][n];
        __nv_bfloat16 h = __float2bfloat16_rn(a);
        __nv_bfloat16 l = __float2bfloat16_rn(a - __bfloat162float(h));
        size_t o = (size_t)(n0 + n) * KDIM + k0 + tx;
        hi[o] = h;
        lo[o] = l;
    }
}

// ---------------------------------------------------------------------------
// HMMA GEMM (R7-exact WIN config): cp.async 3-stage, 2 CTAs/SM, k-chunk 16.
// ---------------------------------------------------------------------------
#define RSTR 24
#define TILE_E (128 * RSTR)
#define STAGE_E (4 * TILE_E)
#define STAGE_B (STAGE_E * 2)          // 24576 bytes
#define NSTAGE 3
#define GEMM_SMEM (NSTAGE * STAGE_B)   // 73728 bytes
#define OFF_AH 0
#define OFF_AL TILE_E
#define OFF_BH (2 * TILE_E)
#define OFF_BL (3 * TILE_E)

template <int MODE>
__global__ void __launch_bounds__(256, 2)
hmma_gemm_kernel(const float* __restrict__ bias, float* __restrict__ Cout, int Nc)
{
    extern __shared__ __nv_bfloat16 smb[];
    const uint32_t su = smem_u32(smb);

    const __nv_bfloat16* Bhi = (MODE == 0) ? g_wqhi : g_wphi;
    const __nv_bfloat16* Blo = (MODE == 0) ? g_wqlo : g_wplo;

    const int tid = threadIdx.x;
    const int wid = tid >> 5;
    const int lane = tid & 31;
    const int wm = wid & 1;
    const int wn = wid >> 1;
    const int bm = blockIdx.y * 128;
    const int bn = blockIdx.x * 128;

    const int grow = tid >> 1;
    const int ghalf = tid & 1;
    const __nv_bfloat16* pAhi = g_ahi + (size_t)(bm + grow) * KDIM + ghalf * 8;
    const __nv_bfloat16* pAlo = g_alo + (size_t)(bm + grow) * KDIM + ghalf * 8;
    const __nv_bfloat16* pBhi = Bhi + (size_t)(bn + grow) * KDIM + ghalf * 8;
    const __nv_bfloat16* pBlo = Blo + (size_t)(bn + grow) * KDIM + ghalf * 8;
    const uint32_t sstore = (uint32_t)(grow * RSTR + ghalf * 8) * 2;   // bytes

    const uint32_t aAddr = (uint32_t)((wm * 64 + (lane & 15)) * RSTR + (lane >> 4) * 8) * 2;
    const uint32_t bAddr = (uint32_t)((wn * 32 + (lane & 7) + ((lane >> 4) & 1) * 8) * RSTR
                                      + ((lane >> 3) & 1) * 8) * 2;

    float acc[4][4][4];
#pragma unroll
    for (int mf = 0; mf < 4; mf++)
#pragma unroll
        for (int nf = 0; nf < 4; nf++)
#pragma unroll
            for (int e = 0; e < 4; e++) acc[mf][nf][e] = 0.f;

    const int NCHUNK = KDIM / 16;      // 64

#pragma unroll
    for (int c = 0; c < 2; c++) {
        uint32_t sb = su + (uint32_t)c * STAGE_B + sstore;
        int ko = c * 16;
        cpa16(sb + OFF_AH * 2, pAhi + ko);
        cpa16(sb + OFF_AL * 2, pAlo + ko);
        cpa16(sb + OFF_BH * 2, pBhi + ko);
        cpa16(sb + OFF_BL * 2, pBlo + ko);
        cpa_commit();
    }

    for (int c = 0; c < NCHUNK; c++) {
        cpa_wait1();                   // chunk c's copy complete
        __syncthreads();

        if (c + 2 < NCHUNK) {
            int slot = (c + 2) % NSTAGE;
            uint32_t sb = su + (uint32_t)slot * STAGE_B + sstore;
            int ko = (c + 2) * 16;
            cpa16(sb + OFF_AH * 2, pAhi + ko);
            cpa16(sb + OFF_AL * 2, pAlo + ko);
            cpa16(sb + OFF_BH * 2, pBhi + ko);
            cpa16(sb + OFF_BL * 2, pBlo + ko);
        }
        cpa_commit();

        const uint32_t sb = su + (uint32_t)(c % NSTAGE) * STAGE_B;
        uint32_t bh[8], bl[8];
        ldsm4(sb + OFF_BH * 2 + bAddr, bh[0], bh[1], bh[2], bh[3]);
        ldsm4(sb + OFF_BH * 2 + bAddr + 16 * RSTR * 2, bh[4], bh[5], bh[6], bh[7]);
        ldsm4(sb + OFF_BL * 2 + bAddr, bl[0], bl[1], bl[2], bl[3]);
        ldsm4(sb + OFF_BL * 2 + bAddr + 16 * RSTR * 2, bl[4], bl[5], bl[6], bl[7]);

#pragma unroll
        for (int mf = 0; mf < 4; mf++) {
            uint32_t a0, a1, a2, a3;
            ldsm4(sb + OFF_AH * 2 + aAddr + mf * 16 * RSTR * 2, a0, a1, a2, a3);
#pragma unroll
            for (int nf = 0; nf < 4; nf++)
                mma_bf16(acc[mf][nf][0], acc[mf][nf][1], acc[mf][nf][2], acc[mf][nf][3],
                         a0, a1, a2, a3, bh[nf * 2], bh[nf * 2 + 1]);
#pragma unroll
            for (int nf = 0; nf < 4; nf++)
                mma_bf16(acc[mf][nf][0], acc[mf][nf][1], acc[mf][nf][2], acc[mf][nf][3],
                         a0, a1, a2, a3, bl[nf * 2], bl[nf * 2 + 1]);
            ldsm4(sb + OFF_AL * 2 + aAddr + mf * 16 * RSTR * 2, a0, a1, a2, a3);
#pragma unroll
            for (int nf = 0; nf < 4; nf++)
                mma_bf16(acc[mf][nf][0], acc[mf][nf][1], acc[mf][nf][2], acc[mf][nf][3],
                         a0, a1, a2, a3, bh[nf * 2], bh[nf * 2 + 1]);
        }
        __syncthreads();               // done reading slot c%3 before refill
    }

#pragma unroll
    for (int mf = 0; mf < 4; mf++) {
#pragma unroll
        for (int nf = 0; nf < 4; nf++) {
            int m0 = bm + wm * 64 + mf * 16 + (lane >> 2);
            int col = bn + wn * 32 + nf * 8 + (lane & 3) * 2;
            float2 bb = *(const float2*)&bias[col];
            float2 v0, v1;
            v0.x = acc[mf][nf][0] + bb.x;
            v0.y = acc[mf][nf][1] + bb.y;
            v1.x = acc[mf][nf][2] + bb.x;
            v1.y = acc[mf][nf][3] + bb.y;
            if (MODE == 0) {
                int part = col >> 10;
                int h = (col >> 6) & (HEADS - 1);
                int d = col & 63;
                float* base = &g_qkv[(((size_t)part * HEADS + h) * NTOK) * HD + d];
                *(float2*)(base + (size_t)m0 * HD) = v0;
                *(float2*)(base + (size_t)(m0 + 8) * HD) = v1;
            } else {
                *(float2*)&Cout[(size_t)m0 * Nc + col] = v0;
                *(float2*)&Cout[(size_t)(m0 + 8) * Nc + col] = v1;
            }
        }
    }
}

// ---------------------------------------------------------------------------
// LayerNorm + bf16 hi/lo split of q, k, and passthrough split of v.
// ---------------------------------------------------------------------------
__global__ void __launch_bounds__(256)
ln2_kernel(const float* __restrict__ qg, const float* __restrict__ qb,
           const float* __restrict__ kg, const float* __restrict__ kb)
{
    const int HN = HEADS * NTOK;
    int warp = (blockIdx.x * blockDim.x + threadIdx.x) >> 5;
    int lane = threadIdx.x & 31;
    if (warp >= 3 * HN) return;

    const float* v = g_qkv + (size_t)warp * HD;
    float2 x = *(const float2*)&v[lane * 2];
    int part = warp / HN;
    int local = warp - part * HN;

    if (part < 2) {
        float s = x.x + x.y;
#pragma unroll
        for (int o = 16; o; o >>= 1) s += __shfl_xor_sync(0xffffffffu, s, o);
        float mu = s * (1.f / 64.f);
        float dx = x.x - mu, dy = x.y - mu;
        float ss = dx * dx + dy * dy;
#pragma unroll
        for (int o = 16; o; o >>= 1) ss += __shfl_xor_sync(0xffffffffu, ss, o);
        float rstd = rsqrtf(ss * (1.f / 64.f) + 1e-6f);
        const float* g = (part == 0) ? qg : kg;
        const float* b = (part == 0) ? qb : kb;
        x.x = dx * rstd * g[lane * 2] + b[lane * 2];
        x.y = dy * rstd * g[lane * 2 + 1] + b[lane * 2 + 1];
    }

    __nv_bfloat16* hi = (part == 0) ? g_qhi : (part == 1) ? g_khi : g_vhi;
    __nv_bfloat16* lo = (part == 0) ? g_qlo : (part == 1) ? g_klo : g_vlo;
    __nv_bfloat16 h0 = __float2bfloat16_rn(x.x);
    __nv_bfloat16 h1 = __float2bfloat16_rn(x.y);
    __nv_bfloat16 l0 = __float2bfloat16_rn(x.x - __bfloat162float(h0));
    __nv_bfloat16 l1 = __float2bfloat16_rn(x.y - __bfloat162float(h1));
    __nv_bfloat162 ph; ph.x = h0; ph.y = h1;
    __nv_bfloat162 pl; pl.x = l0; pl.y = l1;
    *(__nv_bfloat162*)&hi[(size_t)local * HD + lane * 2] = ph;
    *(__nv_bfloat162*)&lo[(size_t)local * HD + lane * 2] = pl;
}

// ---------------------------------------------------------------------------
// HMMA flash attention, KV-split x2 (R7 attn4 structure: reg Q-hi, reg
// prefetch, smem Q-lo). Epilogue stores UNNORMALIZED fp32 partials + l.
// ---------------------------------------------------------------------------
#define AST 72
#define QLO_ELEMS (224 * AST)
#define KARR (KT * AST)
#define TILE_OFF QLO_ELEMS
#define BIAS_OFF (QLO_ELEMS + 4 * KARR)
#define AT_SMEM_BYTES (BIAS_OFF * 2 + KT * 4 + 16)

__global__ void __launch_bounds__(224, 1)
attn7_kernel()
{
    extern __shared__ __nv_bfloat16 smb2[];
    __nv_bfloat16* Qlo = smb2;
    __nv_bfloat16* Tile = smb2 + TILE_OFF;
    float* Bs = (float*)(smb2 + BIAS_OFF);
    const uint32_t su = smem_u32(smb2);

    const int s = blockIdx.x, h = blockIdx.y, split = blockIdx.z;
    const int tid = threadIdx.x, wid = tid >> 5, lane = tid & 31;
    const int m0 = wid * 32;

    const __nv_bfloat16* qh  = g_qhi + ((size_t)h * NTOK + (size_t)s * PTOK) * HD;
    const __nv_bfloat16* qlg = g_qlo + ((size_t)h * NTOK + (size_t)s * PTOK) * HD;
    const __nv_bfloat16* kh = g_khi + (size_t)h * NTOK * HD;
    const __nv_bfloat16* kl = g_klo + (size_t)h * NTOK * HD;
    const __nv_bfloat16* vh = g_vhi + (size_t)h * NTOK * HD;
    const __nv_bfloat16* vl = g_vlo + (size_t)h * NTOK * HD;

    // Qlo -> smem
    {
        int row = tid;
        int srcr = row < PTOK ? row : PTOK - 1;
        const uint4* p = (const uint4*)(qlg + (size_t)srcr * HD);
#pragma unroll
        for (int j = 0; j < 8; j++)
            *(uint4*)&Qlo[row * AST + j * 8] = p[j];
    }

    // Qhi fragments in registers
    uint32_t qf[2][4][4];
    {
        int r = lane >> 2, c2 = (lane & 3) * 2;
#pragma unroll
        for (int mf = 0; mf < 2; mf++) {
            int r0 = m0 + mf * 16 + r;
            int r1 = r0 + 8;
            if (r0 > PTOK - 1) r0 = PTOK - 1;
            if (r1 > PTOK - 1) r1 = PTOK - 1;
#pragma unroll
            for (int kf = 0; kf < 4; kf++) {
                int c0 = kf * 16 + c2;
                qf[mf][kf][0] = *(const uint32_t*)(qh + (size_t)r0 * HD + c0);
                qf[mf][kf][1] = *(const uint32_t*)(qh + (size_t)r1 * HD + c0);
                qf[mf][kf][2] = *(const uint32_t*)(qh + (size_t)r0 * HD + c0 + 8);
                qf[mf][kf][3] = *(const uint32_t*)(qh + (size_t)r1 * HD + c0 + 8);
            }
        }
    }

    float o[2][8][4];
    float lsum[2][2];
#pragma unroll
    for (int mf = 0; mf < 2; mf++) {
        lsum[mf][0] = 0.f; lsum[mf][1] = 0.f;
#pragma unroll
        for (int nf = 0; nf < 8; nf++)
#pragma unroll
            for (int e = 0; e < 4; e++) o[mf][nf][e] = 0.f;
    }

    const int pbase = s * MKPAD + split * KVSPL;

    const uint32_t kaddr = su + 2 * (TILE_OFF
        + ((lane & 7) + ((lane >> 4) & 1) * 8) * AST + ((lane >> 3) & 1) * 8);
    const uint32_t vaddr = su + 2 * (TILE_OFF + 2 * KARR
        + ((lane & 7) + ((lane >> 3) & 1) * 8) * AST + ((lane >> 4) & 1) * 8);
    const uint32_t qladdr = su + 2 * ((m0 + (lane & 15)) * AST + (lane >> 4) * 8);

    // prefetch tile 0 (register prefetch, R7-proven)
    uint4 pf[5];
    float pbias = 0.f;
#pragma unroll
    for (int it = 0; it < 5; it++) {
        int slot = tid + it * 224;
        if (slot < 1024) {
            int a = slot >> 8, r = (slot >> 3) & 31, seg = slot & 7;
            int tok = g_gidx2[pbase + r];
            const __nv_bfloat16* bp = (a == 0) ? kh : (a == 1) ? kl : (a == 2) ? vh : vl;
            pf[it] = *(const uint4*)(bp + (size_t)tok * HD + seg * 8);
        }
    }
    if (tid < KT) pbias = g_bias2[pbase + tid];

    for (int t = 0; t < NT_S; t++) {
        __syncthreads();
#pragma unroll
        for (int it = 0; it < 5; it++) {
            int slot = tid + it * 224;
            if (slot < 1024) {
                int a = slot >> 8, r = (slot >> 3) & 31, seg = slot & 7;
                *(uint4*)&Tile[a * KARR + r * AST + seg * 8] = pf[it];
            }
        }
        if (tid < KT) Bs[tid] = pbias;
        __syncthreads();

        if (t + 1 < NT_S) {
            int ib = pbase + (t + 1) * KT;
#pragma unroll
            for (int it = 0; it < 5; it++) {
                int slot = tid + it * 224;
                if (slot < 1024) {
                    int a = slot >> 8, r = (slot >> 3) & 31, seg = slot & 7;
                    int tok = g_gidx2[ib + r];
                    const __nv_bfloat16* bp = (a == 0) ? kh : (a == 1) ? kl
                                             : (a == 2) ? vh : vl;
                    pf[it] = *(const uint4*)(bp + (size_t)tok * HD + seg * 8);
                }
            }
            if (tid < KT) pbias = g_bias2[ib + tid];
        }

        // ---- QK: 3-product bf16 split ----
        float sc[2][4][4];
#pragma unroll
        for (int mf = 0; mf < 2; mf++)
#pragma unroll
            for (int nf = 0; nf < 4; nf++)
#pragma unroll
                for (int e = 0; e < 4; e++) sc[mf][nf][e] = 0.f;

#pragma unroll
        for (int kf = 0; kf < 4; kf++) {
            uint32_t bh0[4], bh1[4], bl0[4], bl1[4];
            ldsm4(kaddr + kf * 32, bh0[0], bh0[1], bh0[2], bh0[3]);
            ldsm4(kaddr + kf * 32 + 16 * AST * 2, bh1[0], bh1[1], bh1[2], bh1[3]);
            ldsm4(kaddr + KARR * 2 + kf * 32, bl0[0], bl0[1], bl0[2], bl0[3]);
            ldsm4(kaddr + KARR * 2 + kf * 32 + 16 * AST * 2, bl1[0], bl1[1], bl1[2], bl1[3]);
#pragma unroll
            for (int mf = 0; mf < 2; mf++) {
                uint32_t q0 = qf[mf][kf][0], q1 = qf[mf][kf][1];
                uint32_t q2 = qf[mf][kf][2], q3 = qf[mf][kf][3];
                mma_bf16(sc[mf][0][0], sc[mf][0][1], sc[mf][0][2], sc[mf][0][3],
                         q0, q1, q2, q3, bh0[0], bh0[1]);
                mma_bf16(sc[mf][1][0], sc[mf][1][1], sc[mf][1][2], sc[mf][1][3],
                         q0, q1, q2, q3, bh0[2], bh0[3]);
                mma_bf16(sc[mf][2][0], sc[mf][2][1], sc[mf][2][2], sc[mf][2][3],
                         q0, q1, q2, q3, bh1[0], bh1[1]);
                mma_bf16(sc[mf][3][0], sc[mf][3][1], sc[mf][3][2], sc[mf][3][3],
                         q0, q1, q2, q3, bh1[2], bh1[3]);
                mma_bf16(sc[mf][0][0], sc[mf][0][1], sc[mf][0][2], sc[mf][0][3],
                         q0, q1, q2, q3, bl0[0], bl0[1]);
                mma_bf16(sc[mf][1][0], sc[mf][1][1], sc[mf][1][2], sc[mf][1][3],
                         q0, q1, q2, q3, bl0[2], bl0[3]);
                mma_bf16(sc[mf][2][0], sc[mf][2][1], sc[mf][2][2], sc[mf][2][3],
                         q0, q1, q2, q3, bl1[0], bl1[1]);
                mma_bf16(sc[mf][3][0], sc[mf][3][1], sc[mf][3][2], sc[mf][3][3],
                         q0, q1, q2, q3, bl1[2], bl1[3]);
                uint32_t ql0, ql1, ql2, ql3;
                ldsm4(qladdr + mf * 16 * AST * 2 + kf * 32, ql0, ql1, ql2, ql3);
                mma_bf16(sc[mf][0][0], sc[mf][0][1], sc[mf][0][2], sc[mf][0][3],
                         ql0, ql1, ql2, ql3, bh0[0], bh0[1]);
                mma_bf16(sc[mf][1][0], sc[mf][1][1], sc[mf][1][2], sc[mf][1][3],
                         ql0, ql1, ql2, ql3, bh0[2], bh0[3]);
                mma_bf16(sc[mf][2][0], sc[mf][2][1], sc[mf][2][2], sc[mf][2][3],
                         ql0, ql1, ql2, ql3, bh1[0], bh1[1]);
                mma_bf16(sc[mf][3][0], sc[mf][3][1], sc[mf][3][2], sc[mf][3][3],
                         ql0, ql1, ql2, ql3, bh1[2], bh1[3]);
            }
        }

        // ---- softmax weights + P split ----
        uint32_t phi[2][2][4], plo[2][2][4];
#pragma unroll
        for (int mf = 0; mf < 2; mf++) {
#pragma unroll
            for (int nf = 0; nf < 4; nf++) {
                float2 bb = *(const float2*)&Bs[nf * 8 + (lane & 3) * 2];
                float p0 = __expf(fmaf(sc[mf][nf][0], 0.125f, bb.x));
                float p1 = __expf(fmaf(sc[mf][nf][1], 0.125f, bb.y));
                float p2 = __expf(fmaf(sc[mf][nf][2], 0.125f, bb.x));
                float p3 = __expf(fmaf(sc[mf][nf][3], 0.125f, bb.y));
                lsum[mf][0] += p0 + p1;
                lsum[mf][1] += p2 + p3;
                uint32_t h01 = pack_bf16(p0, p1);
                uint32_t h23 = pack_bf16(p2, p3);
                __nv_bfloat162 hv01 = *(__nv_bfloat162*)&h01;
                __nv_bfloat162 hv23 = *(__nv_bfloat162*)&h23;
                uint32_t l01 = pack_bf16(p0 - __bfloat162float(hv01.x),
                                         p1 - __bfloat162float(hv01.y));
                uint32_t l23 = pack_bf16(p2 - __bfloat162float(hv23.x),
                                         p3 - __bfloat162float(hv23.y));
                int kf2 = nf >> 1, hf = (nf & 1) * 2;
                phi[mf][kf2][hf] = h01; phi[mf][kf2][hf + 1] = h23;
                plo[mf][kf2][hf] = l01; plo[mf][kf2][hf + 1] = l23;
            }
        }

        // ---- PV: 3-product split, V via ldsm.trans ----
#pragma unroll
        for (int kf = 0; kf < 2; kf++) {
            uint32_t vhf[16], vlf[16];
#pragma unroll
            for (int db = 0; db < 4; db++) {
                ldsm4t(vaddr + kf * (16 * AST * 2) + db * 32,
                       vhf[db * 4], vhf[db * 4 + 1], vhf[db * 4 + 2], vhf[db * 4 + 3]);
                ldsm4t(vaddr + KARR * 2 + kf * (16 * AST * 2) + db * 32,
                       vlf[db * 4], vlf[db * 4 + 1], vlf[db * 4 + 2], vlf[db * 4 + 3]);
            }
#pragma unroll
            for (int mf = 0; mf < 2; mf++) {
#pragma unroll
                for (int nfd = 0; nfd < 8; nfd++) {
                    int vi = (nfd >> 1) * 4 + (nfd & 1) * 2;
                    mma_bf16(o[mf][nfd][0], o[mf][nfd][1], o[mf][nfd][2], o[mf][nfd][3],
                             phi[mf][kf][0], phi[mf][kf][1], phi[mf][kf][2], phi[mf][kf][3],
                             vhf[vi], vhf[vi + 1]);
                    mma_bf16(o[mf][nfd][0], o[mf][nfd][1], o[mf][nfd][2], o[mf][nfd][3],
                             phi[mf][kf][0], phi[mf][kf][1], phi[mf][kf][2], phi[mf][kf][3],
                             vlf[vi], vlf[vi + 1]);
                    mma_bf16(o[mf][nfd][0], o[mf][nfd][1], o[mf][nfd][2], o[mf][nfd][3],
                             plo[mf][kf][0], plo[mf][kf][1], plo[mf][kf][2], plo[mf][kf][3],
                             vhf[vi], vhf[vi + 1]);
                }
            }
        }
    }

    // reduce l over the 4 lanes sharing each row
#pragma unroll
    for (int mf = 0; mf < 2; mf++) {
#pragma unroll
        for (int j = 0; j < 2; j++) {
            float v = lsum[mf][j];
            v += __shfl_xor_sync(0xffffffffu, v, 1);
            v += __shfl_xor_sync(0xffffffffu, v, 2);
            lsum[mf][j] = v;
        }
    }

    // epilogue: store UNNORMALIZED partials (fp32) + row sums
    {
        int r = lane >> 2, c2 = (lane & 3) * 2;
        const size_t rrbase = ((size_t)(split * SFR + s) * HEADS + h) * PTOK;
#pragma unroll
        for (int mf = 0; mf < 2; mf++) {
            int rowq0 = m0 + mf * 16 + r;
            int rowq1 = rowq0 + 8;
            if (rowq0 < PTOK) {
                float* dst = g_pacc + (rrbase + rowq0) * HD + c2;
#pragma unroll
                for (int nfd = 0; nfd < 8; nfd++) {
                    float2 v; v.x = o[mf][nfd][0]; v.y = o[mf][nfd][1];
                    *(float2*)(dst + nfd * 8) = v;
                }
                if ((lane & 3) == 0) g_pl[rrbase + rowq0] = lsum[mf][0];
            }
            if (rowq1 < PTOK) {
                float* dst = g_pacc + (rrbase + rowq1) * HD + c2;
#pragma unroll
                for (int nfd = 0; nfd < 8; nfd++) {
                    float2 v; v.x = o[mf][nfd][2]; v.y = o[mf][nfd][3];
                    *(float2*)(dst + nfd * 8) = v;
                }
                if ((lane & 3) == 0) g_pl[rrbase + rowq1] = lsum[mf][1];
            }
        }
    }
}

// ---------------------------------------------------------------------------
// Combine split partials: (n0+n1)/(l0+l1), split to bf16 hi/lo into
// token-major g_ahi/g_alo for the projection GEMM.
// ---------------------------------------------------------------------------
__global__ void __launch_bounds__(256)
combine_kernel()
{
    int idx = blockIdx.x * blockDim.x + threadIdx.x;
    const int total = SFR * HEADS * PTOK * (HD / 4);
    if (idx >= total) return;
    int c4 = idx & 15;
    int shp = idx >> 4;                      // (s*HEADS+h)*PTOK + p
    size_t row0 = shp;
    size_t row1 = (size_t)SFR * HEADS * PTOK + shp;
    float4 a = ((const float4*)(g_pacc + row0 * HD))[c4];
    float4 b = ((const float4*)(g_pacc + row1 * HD))[c4];
    float inv = 1.f / (g_pl[row0] + g_pl[row1]);
    float f0 = (a.x + b.x) * inv;
    float f1 = (a.y + b.y) * inv;
    float f2 = (a.z + b.z) * inv;
    float f3 = (a.w + b.w) * inv;
    int p = shp % PTOK;
    int sh = shp / PTOK;
    int hh = sh % HEADS;
    int ss = sh / HEADS;
    size_t base = (size_t)(ss * PTOK + p) * CDIM + hh * HD + c4 * 4;
    uint32_t h01 = pack_bf16(f0, f1);
    uint32_t h23 = pack_bf16(f2, f3);
    __nv_bfloat162 hv01 = *(__nv_bfloat162*)&h01;
    __nv_bfloat162 hv23 = *(__nv_bfloat162*)&h23;
    uint32_t l01 = pack_bf16(f0 - __bfloat162float(hv01.x),
                             f1 - __bfloat162float(hv01.y));
    uint32_t l23 = pack_bf16(f2 - __bfloat162float(hv23.x),
                             f3 - __bfloat162float(hv23.y));
    *(uint32_t*)&g_ahi[base] = h01;
    *(uint32_t*)&g_ahi[base + 2] = h23;
    *(uint32_t*)&g_alo[base] = l01;
    *(uint32_t*)&g_alo[base + 2] = l23;
}

// ---------------------------------------------------------------------------
extern "C" void kernel_launch(void* const* d_in, const int* in_sizes, int n_in,
                              void* d_out, int out_size)
{
    const float* x     = (const float*)d_in[0];
    const float* Wqkv  = (const float*)d_in[1];
    const float* bqkv  = (const float*)d_in[2];
    const float* qg    = (const float*)d_in[3];
    const float* qb    = (const float*)d_in[4];
    const float* kg    = (const float*)d_in[5];
    const float* kb    = (const float*)d_in[6];
    const float* Wproj = (const float*)d_in[7];
    const float* bproj = (const float*)d_in[8];
    const int*   gidx  = (const int*)d_in[9];
    const float* abias = (const float*)d_in[10];
    float* out = (float*)d_out;

    static int attr_set = 0;
    if (!attr_set) {
        cudaFuncSetAttribute(hmma_gemm_kernel<0>,
                             cudaFuncAttributeMaxDynamicSharedMemorySize, GEMM_SMEM);
        cudaFuncSetAttribute(hmma_gemm_kernel<1>,
                             cudaFuncAttributeMaxDynamicSharedMemorySize, GEMM_SMEM);
        cudaFuncSetAttribute(attn7_kernel,
                             cudaFuncAttributeMaxDynamicSharedMemorySize, AT_SMEM_BYTES);
        attr_set = 1;
    }

    const int n4 = NTOK * KDIM / 4;

    // 0) prep: split x, pad gather/bias, transpose+split weights
    split_kernel<<<n4 / 256, 256>>>(x, n4);
    pad_kernel<<<(SFR * MKPAD + 255) / 256, 256>>>(gidx, abias);
    wsplit_kernel<0><<<dim3(NQKV / 32, KDIM / 32), 256>>>(Wqkv, NQKV);
    wsplit_kernel<1><<<dim3(1024 / 32, KDIM / 32), 256>>>(Wproj, 1024);

    // 1) QKV GEMM -> g_qkv fp32
    hmma_gemm_kernel<0><<<dim3(NQKV / 128, NTOK / 128), 256, GEMM_SMEM>>>(
        bqkv, nullptr, NQKV);

    // 2) LayerNorm + bf16 hi/lo split of q/k/v
    {
        int nvec = 3 * HEADS * NTOK;
        ln2_kernel<<<(nvec * 32 + 255) / 256, 256>>>(qg, qb, kg, kb);
    }

    // 3) HMMA flash attention, KV-split x2 -> fp32 partials
    attn7_kernel<<<dim3(SFR, HEADS, NSPL), 224, AT_SMEM_BYTES>>>();

    // 3b) combine partials -> g_ahi/g_alo
    {
        const int total = SFR * HEADS * PTOK * (HD / 4);
        combine_kernel<<<(total + 255) / 256, 256>>>();
    }

    // 4) proj GEMM -> d_out
    hmma_gemm_kernel<1><<<dim3(1024 / 128, NTOK / 128), 256, GEMM_SMEM>>>(
        bproj, out, 1024);
}